// round 1
// baseline (speedup 1.0000x reference)
#include <cuda_runtime.h>

// Problem constants (fixed by the reference: B=8, S=4096, D=512, H=1024, E=8, K=2)
#define NUM_TOK 32768
#define DDIM 512
#define HDIM 1024
#define NEXP 8

// -------- device scratch (static; no runtime allocation) --------
__device__ int   g_cnt[NEXP];                       // tokens assigned per expert
__device__ int   g_list[NEXP][NUM_TOK];             // packed slot = token*2 + k
__device__ float g_gatev[NUM_TOK * 2];              // gate per slot
__device__ float g_hbuf[(size_t)NUM_TOK * 2 * HDIM]; // hidden activations per slot (268 MB)

// -------- zero out + counters --------
__global__ void zero_kernel(float* __restrict__ out, long long n) {
    long long i = (long long)blockIdx.x * blockDim.x + threadIdx.x;
    long long stride = (long long)gridDim.x * blockDim.x;
    for (; i < n; i += stride) out[i] = 0.0f;
    if (blockIdx.x == 0 && threadIdx.x < NEXP) g_cnt[threadIdx.x] = 0;
}

// -------- router: one warp per token --------
__global__ void router_kernel(const float* __restrict__ x,
                              const float* __restrict__ rw,
                              const float* __restrict__ rb) {
    int gw   = (blockIdx.x * blockDim.x + threadIdx.x) >> 5;
    int lane = threadIdx.x & 31;
    if (gw >= NUM_TOK) return;
    const float* xr = x + (size_t)gw * DDIM;

    float acc[NEXP];
#pragma unroll
    for (int e = 0; e < NEXP; e++) acc[e] = 0.0f;

    for (int d = lane; d < DDIM; d += 32) {
        float xv = xr[d];
        const float* r = rw + (size_t)d * NEXP;
#pragma unroll
        for (int e = 0; e < NEXP; e++) acc[e] = fmaf(xv, r[e], acc[e]);
    }
#pragma unroll
    for (int off = 16; off > 0; off >>= 1) {
#pragma unroll
        for (int e = 0; e < NEXP; e++)
            acc[e] += __shfl_down_sync(0xffffffffu, acc[e], off);
    }
    if (lane == 0) {
#pragma unroll
        for (int e = 0; e < NEXP; e++) acc[e] += rb[e];
        // top-2, ties -> lowest index (matches jax top_k stability)
        int i0 = 0; float v0 = acc[0];
#pragma unroll
        for (int e = 1; e < NEXP; e++) if (acc[e] > v0) { v0 = acc[e]; i0 = e; }
        int i1 = -1; float v1 = -3.0e38f;
#pragma unroll
        for (int e = 0; e < NEXP; e++) if (e != i0 && acc[e] > v1) { v1 = acc[e]; i1 = e; }
        // softmax over {v0, v1}; v0 >= v1
        float e1  = expf(v1 - v0);
        float inv = 1.0f / (1.0f + e1);
        float g0  = inv, g1 = e1 * inv;

        int p0 = atomicAdd(&g_cnt[i0], 1);
        g_list[i0][p0]     = gw * 2;
        g_gatev[gw * 2]    = g0;
        int p1 = atomicAdd(&g_cnt[i1], 1);
        g_list[i1][p1]     = gw * 2 + 1;
        g_gatev[gw * 2 + 1] = g1;
    }
}

// -------- grouped SGEMM 1: h = relu(x[idx] @ w1[e] + b1[e]) --------
// 128x128 tile, BK=8, 256 threads, 8x8 per thread (4x4 quadrants)
__global__ __launch_bounds__(256)
void gemm1_kernel(const float* __restrict__ x,
                  const float* __restrict__ w1,
                  const float* __restrict__ b1) {
    int e   = blockIdx.y;
    int cnt = g_cnt[e];
    int m0  = blockIdx.x * 128;
    if (m0 >= cnt) return;
    int rows = cnt - m0; if (rows > 128) rows = 128;
    int n0 = blockIdx.z * 128;

    __shared__ __align__(16) float As[8][132];   // padded: conflict-free transposed stores
    __shared__ __align__(16) float Bs[8][128];
    __shared__ int s_slot[128];
    __shared__ int s_tok[128];

    int tid = threadIdx.x;
    if (tid < 128) {
        int r = tid < rows ? tid : rows - 1;
        int slot = g_list[e][m0 + r];
        s_slot[tid] = slot;
        s_tok[tid]  = slot >> 1;
    }
    __syncthreads();

    const float* Bg = w1 + (size_t)e * DDIM * HDIM + n0;  // B[k][n] = Bg[k*HDIM + n]
    int arow  = tid >> 1;          // 0..127
    int acol4 = (tid & 1) << 2;    // 0 or 4
    int brow  = tid >> 5;          // 0..7
    int bcol4 = (tid & 31) << 2;   // 0..124
    int tx = tid & 15, ty = tid >> 4;

    const float* Arow = x + (size_t)s_tok[arow] * DDIM + acol4;

    float acc[8][8];
#pragma unroll
    for (int i = 0; i < 8; i++)
#pragma unroll
        for (int j = 0; j < 8; j++) acc[i][j] = 0.0f;

    for (int k0 = 0; k0 < DDIM; k0 += 8) {
        float4 av = *(const float4*)(Arow + k0);
        float4 bv = *(const float4*)(Bg + (size_t)(k0 + brow) * HDIM + bcol4);
        As[acol4 + 0][arow] = av.x;
        As[acol4 + 1][arow] = av.y;
        As[acol4 + 2][arow] = av.z;
        As[acol4 + 3][arow] = av.w;
        *(float4*)&Bs[brow][bcol4] = bv;
        __syncthreads();
#pragma unroll
        for (int k = 0; k < 8; k++) {
            float4 a0 = *(const float4*)&As[k][ty * 4];
            float4 a1 = *(const float4*)&As[k][64 + ty * 4];
            float4 b0 = *(const float4*)&Bs[k][tx * 4];
            float4 b1v = *(const float4*)&Bs[k][64 + tx * 4];
            float a[8] = {a0.x, a0.y, a0.z, a0.w, a1.x, a1.y, a1.z, a1.w};
            float b[8] = {b0.x, b0.y, b0.z, b0.w, b1v.x, b1v.y, b1v.z, b1v.w};
#pragma unroll
            for (int i = 0; i < 8; i++)
#pragma unroll
                for (int j = 0; j < 8; j++)
                    acc[i][j] = fmaf(a[i], b[j], acc[i][j]);
        }
        __syncthreads();
    }

    // epilogue: bias + relu -> g_hbuf[slot][n0 + col]
    const float* b1e = b1 + (size_t)e * HDIM + n0;
    float bias[8];
#pragma unroll
    for (int j = 0; j < 8; j++) {
        int c = (j < 4) ? (tx * 4 + j) : (64 + tx * 4 + (j - 4));
        bias[j] = b1e[c];
    }
#pragma unroll
    for (int i = 0; i < 8; i++) {
        int r = (i < 4) ? (ty * 4 + i) : (64 + ty * 4 + (i - 4));
        if (r < rows) {
            float* hrow = g_hbuf + (size_t)s_slot[r] * HDIM + n0;
#pragma unroll
            for (int jq = 0; jq < 2; jq++) {
                float4 v;
                v.x = fmaxf(acc[i][jq * 4 + 0] + bias[jq * 4 + 0], 0.0f);
                v.y = fmaxf(acc[i][jq * 4 + 1] + bias[jq * 4 + 1], 0.0f);
                v.z = fmaxf(acc[i][jq * 4 + 2] + bias[jq * 4 + 2], 0.0f);
                v.w = fmaxf(acc[i][jq * 4 + 3] + bias[jq * 4 + 3], 0.0f);
                *(float4*)&hrow[jq * 64 + tx * 4] = v;
            }
        }
    }
}

// -------- grouped SGEMM 2: out[tok] += g * (h[slot] @ w2[e] + b2[e]) --------
__global__ __launch_bounds__(256)
void gemm2_kernel(const float* __restrict__ w2,
                  const float* __restrict__ b2,
                  float* __restrict__ out) {
    int e   = blockIdx.y;
    int cnt = g_cnt[e];
    int m0  = blockIdx.x * 128;
    if (m0 >= cnt) return;
    int rows = cnt - m0; if (rows > 128) rows = 128;
    int n0 = blockIdx.z * 128;

    __shared__ __align__(16) float As[8][132];
    __shared__ __align__(16) float Bs[8][128];
    __shared__ int   s_slot[128];
    __shared__ float s_gate[128];

    int tid = threadIdx.x;
    if (tid < 128) {
        int r = tid < rows ? tid : rows - 1;
        int slot = g_list[e][m0 + r];
        s_slot[tid] = slot;
        s_gate[tid] = g_gatev[slot];
    }
    __syncthreads();

    const float* Bg = w2 + (size_t)e * HDIM * DDIM + n0;  // B[k][n] = Bg[k*DDIM + n]
    int arow  = tid >> 1;
    int acol4 = (tid & 1) << 2;
    int brow  = tid >> 5;
    int bcol4 = (tid & 31) << 2;
    int tx = tid & 15, ty = tid >> 4;

    const float* Arow = g_hbuf + (size_t)s_slot[arow] * HDIM + acol4;

    float acc[8][8];
#pragma unroll
    for (int i = 0; i < 8; i++)
#pragma unroll
        for (int j = 0; j < 8; j++) acc[i][j] = 0.0f;

    for (int k0 = 0; k0 < HDIM; k0 += 8) {
        float4 av = *(const float4*)(Arow + k0);
        float4 bv = *(const float4*)(Bg + (size_t)(k0 + brow) * DDIM + bcol4);
        As[acol4 + 0][arow] = av.x;
        As[acol4 + 1][arow] = av.y;
        As[acol4 + 2][arow] = av.z;
        As[acol4 + 3][arow] = av.w;
        *(float4*)&Bs[brow][bcol4] = bv;
        __syncthreads();
#pragma unroll
        for (int k = 0; k < 8; k++) {
            float4 a0 = *(const float4*)&As[k][ty * 4];
            float4 a1 = *(const float4*)&As[k][64 + ty * 4];
            float4 b0 = *(const float4*)&Bs[k][tx * 4];
            float4 b1v = *(const float4*)&Bs[k][64 + tx * 4];
            float a[8] = {a0.x, a0.y, a0.z, a0.w, a1.x, a1.y, a1.z, a1.w};
            float b[8] = {b0.x, b0.y, b0.z, b0.w, b1v.x, b1v.y, b1v.z, b1v.w};
#pragma unroll
            for (int i = 0; i < 8; i++)
#pragma unroll
                for (int j = 0; j < 8; j++)
                    acc[i][j] = fmaf(a[i], b[j], acc[i][j]);
        }
        __syncthreads();
    }

    // epilogue: gate-scaled bias-add, atomic accumulate into out
    const float* b2e = b2 + (size_t)e * DDIM + n0;
    float bias[8];
#pragma unroll
    for (int j = 0; j < 8; j++) {
        int c = (j < 4) ? (tx * 4 + j) : (64 + tx * 4 + (j - 4));
        bias[j] = b2e[c];
    }
#pragma unroll
    for (int i = 0; i < 8; i++) {
        int r = (i < 4) ? (ty * 4 + i) : (64 + ty * 4 + (i - 4));
        if (r < rows) {
            int   tok = s_slot[r] >> 1;
            float g   = s_gate[r];
            float* orow = out + (size_t)tok * DDIM + n0;
#pragma unroll
            for (int j = 0; j < 8; j++) {
                int c = (j < 4) ? (tx * 4 + j) : (64 + tx * 4 + (j - 4));
                atomicAdd(&orow[c], g * (acc[i][j] + bias[j]));
            }
        }
    }
}

// -------- expert usage tail --------
__global__ void usage_kernel(float* __restrict__ out, long long out_size) {
    int e = threadIdx.x;
    if (e < NEXP && out_size >= (long long)NUM_TOK * DDIM + NEXP)
        out[(long long)NUM_TOK * DDIM + e] = (float)g_cnt[e];
}

extern "C" void kernel_launch(void* const* d_in, const int* in_sizes, int n_in,
                              void* d_out, int out_size) {
    const float* x  = (const float*)d_in[0];
    const float* rw = (const float*)d_in[1];
    const float* rb = (const float*)d_in[2];
    const float* w1 = (const float*)d_in[3];
    const float* b1 = (const float*)d_in[4];
    const float* w2 = (const float*)d_in[5];
    const float* b2 = (const float*)d_in[6];
    float* out = (float*)d_out;

    zero_kernel<<<2048, 256>>>(out, (long long)NUM_TOK * DDIM);
    router_kernel<<<(NUM_TOK * 32 + 255) / 256, 256>>>(x, rw, rb);
    gemm1_kernel<<<dim3(256, NEXP, HDIM / 128), 256>>>(x, w1, b1);
    gemm2_kernel<<<dim3(256, NEXP, DDIM / 128), 256>>>(w2, b2, out);
    usage_kernel<<<1, 32>>>(out, (long long)out_size);
}

// round 2
// speedup vs baseline: 1.8096x; 1.8096x over previous
#include <cuda_runtime.h>
#include <cstdint>

// Problem constants (B=8, S=4096, D=512, H=1024, E=8, K=2)
#define NUM_TOK 32768
#define DDIM 512
#define HDIM 1024
#define NEXP 8

#define BM 128
#define BN 128
#define BK 16
#define SSTR 136   // smem row stride (floats); 136 % 32 == 8 -> conflict-free patterns

// -------- device scratch --------
__device__ int   g_cnt[NEXP];
__device__ int   g_list[NEXP][NUM_TOK];
__device__ float g_gatev[NUM_TOK * 2];
__device__ float g_hbuf[(size_t)NUM_TOK * 2 * HDIM];

// -------- helpers --------
__device__ __forceinline__ float tf32r(float x) {
    uint32_t u;
    asm("cvt.rna.tf32.f32 %0, %1;" : "=r"(u) : "f"(x));
    return __uint_as_float(u);
}

__device__ __forceinline__ void mma_tf32(float* c, const uint32_t* a, const uint32_t* b) {
    asm volatile(
        "mma.sync.aligned.m16n8k8.row.col.f32.tf32.tf32.f32 "
        "{%0,%1,%2,%3}, {%4,%5,%6,%7}, {%8,%9}, {%0,%1,%2,%3};\n"
        : "+f"(c[0]), "+f"(c[1]), "+f"(c[2]), "+f"(c[3])
        : "r"(a[0]), "r"(a[1]), "r"(a[2]), "r"(a[3]),
          "r"(b[0]), "r"(b[1]));
}

// -------- zero out + counters --------
__global__ void zero_kernel(float* __restrict__ out, long long n) {
    long long i = (long long)blockIdx.x * blockDim.x + threadIdx.x;
    long long stride = (long long)gridDim.x * blockDim.x;
    for (; i < n; i += stride) out[i] = 0.0f;
    if (blockIdx.x == 0 && threadIdx.x < NEXP) g_cnt[threadIdx.x] = 0;
}

// -------- router: one warp per token --------
__global__ void router_kernel(const float* __restrict__ x,
                              const float* __restrict__ rw,
                              const float* __restrict__ rb) {
    int gw   = (blockIdx.x * blockDim.x + threadIdx.x) >> 5;
    int lane = threadIdx.x & 31;
    if (gw >= NUM_TOK) return;
    const float* xr = x + (size_t)gw * DDIM;

    float acc[NEXP];
#pragma unroll
    for (int e = 0; e < NEXP; e++) acc[e] = 0.0f;
    for (int d = lane; d < DDIM; d += 32) {
        float xv = xr[d];
        const float* r = rw + (size_t)d * NEXP;
#pragma unroll
        for (int e = 0; e < NEXP; e++) acc[e] = fmaf(xv, r[e], acc[e]);
    }
#pragma unroll
    for (int off = 16; off > 0; off >>= 1) {
#pragma unroll
        for (int e = 0; e < NEXP; e++)
            acc[e] += __shfl_down_sync(0xffffffffu, acc[e], off);
    }
    if (lane == 0) {
#pragma unroll
        for (int e = 0; e < NEXP; e++) acc[e] += rb[e];
        int i0 = 0; float v0 = acc[0];
#pragma unroll
        for (int e = 1; e < NEXP; e++) if (acc[e] > v0) { v0 = acc[e]; i0 = e; }
        int i1 = -1; float v1 = -3.0e38f;
#pragma unroll
        for (int e = 0; e < NEXP; e++) if (e != i0 && acc[e] > v1) { v1 = acc[e]; i1 = e; }
        float e1  = expf(v1 - v0);
        float inv = 1.0f / (1.0f + e1);
        int p0 = atomicAdd(&g_cnt[i0], 1);
        g_list[i0][p0] = gw * 2;
        g_gatev[gw * 2] = inv;
        int p1 = atomicAdd(&g_cnt[i1], 1);
        g_list[i1][p1] = gw * 2 + 1;
        g_gatev[gw * 2 + 1] = e1 * inv;
    }
}

// ============================================================
// GEMM1: h[slot] = relu( x[tok] @ w1[e] + b1[e] )   (tf32 mma)
// ============================================================
__global__ __launch_bounds__(256, 2)
void gemm1_kernel(const float* __restrict__ x,
                  const float* __restrict__ w1,
                  const float* __restrict__ b1) {
    int e   = blockIdx.y;
    int cnt = g_cnt[e];
    int m0  = blockIdx.x * BM;
    if (m0 >= cnt) return;
    int rows = min(cnt - m0, BM);
    int n0 = blockIdx.z * BN;

    __shared__ float As[2][BK][SSTR];   // [k][m] transposed
    __shared__ float Bs[2][BK][SSTR];   // [k][n]
    __shared__ int s_slot[BM];
    __shared__ int s_tok[BM];

    int tid = threadIdx.x;
    if (tid < BM) {
        int r = tid < rows ? tid : rows - 1;
        int slot = g_list[e][m0 + r];
        s_slot[tid] = slot;
        s_tok[tid]  = slot >> 1;
    }
    __syncthreads();

    const float* Bg = w1 + (size_t)e * DDIM * HDIM + n0;   // B[k][n], ld = HDIM

    // loader assignment
    int lr  = tid & 127;              // A row in tile (lanes consecutive -> conflict-free STS)
    int lkv = (tid >> 7) * 4;         // 0 or 4; +8 covers 8..15
    int lc  = (tid & 31) * 4;         // B col
    int lk  = tid >> 5;               // B row 0..7; +8 covers 8..15
    const float* aRow = x + (size_t)s_tok[lr] * DDIM;

    // warp / lane
    int wid = tid >> 5, lane = tid & 31;
    int g = lane >> 2, t = lane & 3;
    int wm = (wid & 1) * 64;
    int wn = (wid >> 1) * 32;

    float acc[4][4][4] = {};

    float4 av0, av1, bv0, bv1;
    av0 = *(const float4*)(aRow + lkv);
    av1 = *(const float4*)(aRow + lkv + 8);
    bv0 = *(const float4*)(Bg + (size_t)lk * HDIM + lc);
    bv1 = *(const float4*)(Bg + (size_t)(lk + 8) * HDIM + lc);

    // sts closures
    auto stsA = [&](int b, const float4& v0, const float4& v1) {
        As[b][lkv + 0][lr] = tf32r(v0.x);
        As[b][lkv + 1][lr] = tf32r(v0.y);
        As[b][lkv + 2][lr] = tf32r(v0.z);
        As[b][lkv + 3][lr] = tf32r(v0.w);
        As[b][lkv + 8][lr] = tf32r(v1.x);
        As[b][lkv + 9][lr] = tf32r(v1.y);
        As[b][lkv +10][lr] = tf32r(v1.z);
        As[b][lkv +11][lr] = tf32r(v1.w);
    };
    auto stsB = [&](int b, const float4& v0, const float4& v1) {
        float4 c0 = make_float4(tf32r(v0.x), tf32r(v0.y), tf32r(v0.z), tf32r(v0.w));
        float4 c1 = make_float4(tf32r(v1.x), tf32r(v1.y), tf32r(v1.z), tf32r(v1.w));
        *(float4*)&Bs[b][lk][lc]     = c0;
        *(float4*)&Bs[b][lk + 8][lc] = c1;
    };

    stsA(0, av0, av1);
    stsB(0, bv0, bv1);
    __syncthreads();

    const int KT = DDIM / BK;   // 32
    int buf = 0;
    for (int kb = 0; kb < KT; kb++) {
        if (kb + 1 < KT) {
            int k0 = (kb + 1) * BK;
            av0 = *(const float4*)(aRow + k0 + lkv);
            av1 = *(const float4*)(aRow + k0 + lkv + 8);
            bv0 = *(const float4*)(Bg + (size_t)(k0 + lk) * HDIM + lc);
            bv1 = *(const float4*)(Bg + (size_t)(k0 + lk + 8) * HDIM + lc);
        }
#pragma unroll
        for (int ks = 0; ks < BK; ks += 8) {
            uint32_t a[4][4], bf[4][2];
#pragma unroll
            for (int i = 0; i < 4; i++) {
                int m = wm + 16 * i;
                a[i][0] = __float_as_uint(As[buf][ks + t][m + g]);
                a[i][1] = __float_as_uint(As[buf][ks + t][m + g + 8]);
                a[i][2] = __float_as_uint(As[buf][ks + t + 4][m + g]);
                a[i][3] = __float_as_uint(As[buf][ks + t + 4][m + g + 8]);
            }
#pragma unroll
            for (int j = 0; j < 4; j++) {
                int n = wn + 8 * j + g;
                bf[j][0] = __float_as_uint(Bs[buf][ks + t][n]);
                bf[j][1] = __float_as_uint(Bs[buf][ks + t + 4][n]);
            }
#pragma unroll
            for (int i = 0; i < 4; i++)
#pragma unroll
                for (int j = 0; j < 4; j++)
                    mma_tf32(acc[i][j], a[i], bf[j]);
        }
        if (kb + 1 < KT) {
            stsA(buf ^ 1, av0, av1);
            stsB(buf ^ 1, bv0, bv1);
        }
        __syncthreads();
        buf ^= 1;
    }

    // epilogue: bias + relu -> g_hbuf
    const float* b1e = b1 + (size_t)e * HDIM + n0;
#pragma unroll
    for (int i = 0; i < 4; i++) {
#pragma unroll
        for (int rr = 0; rr < 2; rr++) {
            int r = wm + 16 * i + g + rr * 8;
            if (r < rows) {
                float* hrow = g_hbuf + (size_t)s_slot[r] * HDIM + n0;
#pragma unroll
                for (int j = 0; j < 4; j++) {
                    int c = wn + 8 * j + 2 * t;
                    float v0 = acc[i][j][rr * 2 + 0] + b1e[c];
                    float v1 = acc[i][j][rr * 2 + 1] + b1e[c + 1];
                    float2 o = make_float2(fmaxf(v0, 0.0f), fmaxf(v1, 0.0f));
                    *(float2*)&hrow[c] = o;
                }
            }
        }
    }
}

// ============================================================
// GEMM2: out[tok] += gate * ( h[slot] @ w2[e] + b2[e] )
// ============================================================
__global__ __launch_bounds__(256, 2)
void gemm2_kernel(const float* __restrict__ w2,
                  const float* __restrict__ b2,
                  float* __restrict__ out) {
    int e   = blockIdx.y;
    int cnt = g_cnt[e];
    int m0  = blockIdx.x * BM;
    if (m0 >= cnt) return;
    int rows = min(cnt - m0, BM);
    int n0 = blockIdx.z * BN;

    __shared__ float As[2][BK][SSTR];
    __shared__ float Bs[2][BK][SSTR];
    __shared__ int   s_slot[BM];
    __shared__ float s_gate[BM];

    int tid = threadIdx.x;
    if (tid < BM) {
        int r = tid < rows ? tid : rows - 1;
        int slot = g_list[e][m0 + r];
        s_slot[tid] = slot;
        s_gate[tid] = g_gatev[slot];
    }
    __syncthreads();

    const float* Bg = w2 + (size_t)e * HDIM * DDIM + n0;   // ld = DDIM

    int lr  = tid & 127;
    int lkv = (tid >> 7) * 4;
    int lc  = (tid & 31) * 4;
    int lk  = tid >> 5;
    const float* aRow = g_hbuf + (size_t)s_slot[lr] * HDIM;

    int wid = tid >> 5, lane = tid & 31;
    int g = lane >> 2, t = lane & 3;
    int wm = (wid & 1) * 64;
    int wn = (wid >> 1) * 32;

    float acc[4][4][4] = {};

    float4 av0, av1, bv0, bv1;
    av0 = *(const float4*)(aRow + lkv);
    av1 = *(const float4*)(aRow + lkv + 8);
    bv0 = *(const float4*)(Bg + (size_t)lk * DDIM + lc);
    bv1 = *(const float4*)(Bg + (size_t)(lk + 8) * DDIM + lc);

    auto stsA = [&](int b, const float4& v0, const float4& v1) {
        As[b][lkv + 0][lr] = tf32r(v0.x);
        As[b][lkv + 1][lr] = tf32r(v0.y);
        As[b][lkv + 2][lr] = tf32r(v0.z);
        As[b][lkv + 3][lr] = tf32r(v0.w);
        As[b][lkv + 8][lr] = tf32r(v1.x);
        As[b][lkv + 9][lr] = tf32r(v1.y);
        As[b][lkv +10][lr] = tf32r(v1.z);
        As[b][lkv +11][lr] = tf32r(v1.w);
    };
    auto stsB = [&](int b, const float4& v0, const float4& v1) {
        float4 c0 = make_float4(tf32r(v0.x), tf32r(v0.y), tf32r(v0.z), tf32r(v0.w));
        float4 c1 = make_float4(tf32r(v1.x), tf32r(v1.y), tf32r(v1.z), tf32r(v1.w));
        *(float4*)&Bs[b][lk][lc]     = c0;
        *(float4*)&Bs[b][lk + 8][lc] = c1;
    };

    stsA(0, av0, av1);
    stsB(0, bv0, bv1);
    __syncthreads();

    const int KT = HDIM / BK;   // 64
    int buf = 0;
    for (int kb = 0; kb < KT; kb++) {
        if (kb + 1 < KT) {
            int k0 = (kb + 1) * BK;
            av0 = *(const float4*)(aRow + k0 + lkv);
            av1 = *(const float4*)(aRow + k0 + lkv + 8);
            bv0 = *(const float4*)(Bg + (size_t)(k0 + lk) * DDIM + lc);
            bv1 = *(const float4*)(Bg + (size_t)(k0 + lk + 8) * DDIM + lc);
        }
#pragma unroll
        for (int ks = 0; ks < BK; ks += 8) {
            uint32_t a[4][4], bf[4][2];
#pragma unroll
            for (int i = 0; i < 4; i++) {
                int m = wm + 16 * i;
                a[i][0] = __float_as_uint(As[buf][ks + t][m + g]);
                a[i][1] = __float_as_uint(As[buf][ks + t][m + g + 8]);
                a[i][2] = __float_as_uint(As[buf][ks + t + 4][m + g]);
                a[i][3] = __float_as_uint(As[buf][ks + t + 4][m + g + 8]);
            }
#pragma unroll
            for (int j = 0; j < 4; j++) {
                int n = wn + 8 * j + g;
                bf[j][0] = __float_as_uint(Bs[buf][ks + t][n]);
                bf[j][1] = __float_as_uint(Bs[buf][ks + t + 4][n]);
            }
#pragma unroll
            for (int i = 0; i < 4; i++)
#pragma unroll
                for (int j = 0; j < 4; j++)
                    mma_tf32(acc[i][j], a[i], bf[j]);
        }
        if (kb + 1 < KT) {
            stsA(buf ^ 1, av0, av1);
            stsB(buf ^ 1, bv0, bv1);
        }
        __syncthreads();
        buf ^= 1;
    }

    // epilogue: gate-scaled bias add, atomic accumulate
    const float* b2e = b2 + (size_t)e * DDIM + n0;
#pragma unroll
    for (int i = 0; i < 4; i++) {
#pragma unroll
        for (int rr = 0; rr < 2; rr++) {
            int r = wm + 16 * i + g + rr * 8;
            if (r < rows) {
                int   tok = s_slot[r] >> 1;
                float gt  = s_gate[r];
                float* orow = out + (size_t)tok * DDIM + n0;
#pragma unroll
                for (int j = 0; j < 4; j++) {
                    int c = wn + 8 * j + 2 * t;
                    atomicAdd(&orow[c],     gt * (acc[i][j][rr * 2 + 0] + b2e[c]));
                    atomicAdd(&orow[c + 1], gt * (acc[i][j][rr * 2 + 1] + b2e[c + 1]));
                }
            }
        }
    }
}

// -------- expert usage tail --------
__global__ void usage_kernel(float* __restrict__ out, long long out_size) {
    int e = threadIdx.x;
    if (e < NEXP && out_size >= (long long)NUM_TOK * DDIM + NEXP)
        out[(long long)NUM_TOK * DDIM + e] = (float)g_cnt[e];
}

extern "C" void kernel_launch(void* const* d_in, const int* in_sizes, int n_in,
                              void* d_out, int out_size) {
    const float* x  = (const float*)d_in[0];
    const float* rw = (const float*)d_in[1];
    const float* rb = (const float*)d_in[2];
    const float* w1 = (const float*)d_in[3];
    const float* b1 = (const float*)d_in[4];
    const float* w2 = (const float*)d_in[5];
    const float* b2 = (const float*)d_in[6];
    float* out = (float*)d_out;

    zero_kernel<<<2048, 256>>>(out, (long long)NUM_TOK * DDIM);
    router_kernel<<<(NUM_TOK * 32 + 255) / 256, 256>>>(x, rw, rb);
    gemm1_kernel<<<dim3(256, NEXP, HDIM / 128), 256>>>(x, w1, b1);
    gemm2_kernel<<<dim3(256, NEXP, DDIM / 128), 256>>>(w2, b2, out);
    usage_kernel<<<1, 32>>>(out, (long long)out_size);
}